// round 10
// baseline (speedup 1.0000x reference)
#include <cuda_runtime.h>
#include <cuda_fp16.h>
#include <cstdint>

#define NB 16
#define HW 1024
#define CI 512
#define CA 512
#define KL 256

// Scratch (alloc-free: __device__ globals)
__device__ __half g_qh[NB * HW * CA];     // Q (half, from Q GEMM)
__device__ __half g_kh[NB * KL * CA];     // K
__device__ __half g_vh[NB * KL * CA];     // V
__device__ __half g_attnh[NB * HW * CA];  // attention out (half)
__device__ float  g_y[NB * HW * CI];      // O GEMM out (fp32, LN input)
__device__ __half g_imgth[NB * HW * CI];  // img transposed [b][s][c], half
__device__ __half g_audh[NB * KL * CA];   // audio, half
__device__ __half g_wth[4 * 512 * 512];   // weights transposed [n][k], half

// ---------------------------------------------------------------------------
// Helpers
// ---------------------------------------------------------------------------
__device__ __forceinline__ uint32_t smem_u32(const void* p) {
    uint32_t a;
    asm("{ .reg .u64 t; cvta.to.shared.u64 t, %1; cvt.u32.u64 %0, t; }"
        : "=r"(a) : "l"(p));
    return a;
}
#define CP_ASYNC16(dst, src) \
    asm volatile("cp.async.cg.shared.global [%0], [%1], 16;" \
                 :: "r"(dst), "l"(src) : "memory")
#define CP_COMMIT() asm volatile("cp.async.commit_group;" ::: "memory")
#define CP_WAIT(n)  asm volatile("cp.async.wait_group %0;" :: "n"(n) : "memory")

__device__ __forceinline__ void mma_f16(float (&c)[4], const uint32_t (&a)[4],
                                        const uint32_t (&b)[2]) {
    asm volatile(
        "mma.sync.aligned.m16n8k16.row.col.f32.f16.f16.f32 "
        "{%0,%1,%2,%3}, {%4,%5,%6,%7}, {%8,%9}, {%0,%1,%2,%3};"
        : "+f"(c[0]), "+f"(c[1]), "+f"(c[2]), "+f"(c[3])
        : "r"(a[0]), "r"(a[1]), "r"(a[2]), "r"(a[3]), "r"(b[0]), "r"(b[1]));
}

// ---------------------------------------------------------------------------
// Converters
// ---------------------------------------------------------------------------
// img [b][c][s] fp32 -> [b][s][c] half (transpose through smem)
__global__ void cvt_img_t(const float* __restrict__ img) {
    __shared__ float tile[32][33];
    const int c0 = blockIdx.x * 32, s0 = blockIdx.y * 32, b = blockIdx.z;
    const int tx = threadIdx.x, ty = threadIdx.y;
#pragma unroll
    for (int i = 0; i < 4; i++)
        tile[ty + 8 * i][tx] =
            img[((size_t)b * CI + c0 + ty + 8 * i) * HW + s0 + tx];
    __syncthreads();
#pragma unroll
    for (int i = 0; i < 4; i++)
        g_imgth[((size_t)b * HW + s0 + ty + 8 * i) * CI + c0 + tx] =
            __float2half(tile[tx][ty + 8 * i]);
}

// W [k][n] fp32 -> g_wth[z][n][k] half (transpose)
__global__ void cvt_w_t(const float* __restrict__ W0,
                        const float* __restrict__ W1,
                        const float* __restrict__ W2,
                        const float* __restrict__ W3) {
    __shared__ float tile[32][33];
    const int z = blockIdx.z;
    const float* W = (z == 0) ? W0 : (z == 1) ? W1 : (z == 2) ? W2 : W3;
    __half* T = g_wth + (size_t)z * 512 * 512;
    const int n0 = blockIdx.x * 32, k0 = blockIdx.y * 32;
    const int tx = threadIdx.x, ty = threadIdx.y;
#pragma unroll
    for (int i = 0; i < 4; i++)
        tile[ty + 8 * i][tx] = W[(size_t)(k0 + ty + 8 * i) * 512 + n0 + tx];
    __syncthreads();
#pragma unroll
    for (int i = 0; i < 4; i++)
        T[(size_t)(n0 + ty + 8 * i) * 512 + k0 + tx] = __float2half(tile[tx][ty + 8 * i]);
}

// audio fp32 -> half, elementwise
__global__ void cvt_aud(const float4* __restrict__ src) {
    const int i = blockIdx.x * blockDim.x + threadIdx.x;
    const float4 v = src[i];
    __half2* dst = (__half2*)g_audh;
    dst[2 * i] = __floats2half2_rn(v.x, v.y);
    dst[2 * i + 1] = __floats2half2_rn(v.z, v.w);
}

// ---------------------------------------------------------------------------
// HGEMM: C[M,512] = A[M,512] @ Wt^T + bias   (A row-major half, Wt [n][k] half)
// 128x128 tile, BK=64, 256 threads (8 warps 2m x 4n), warp tile 64x32,
// m16n8k16 fp16 MMA, fp32 accum, 2-stage cp.async.
// smem per matrix per stage: [128 rows][36 half2] (32 data + 4 pad).
// MODE 0: A=g_imgth -> g_qh (half)   1: g_audh -> g_kh   2: g_audh -> g_vh
// MODE 3: A=g_attnh -> g_y (fp32)
// ---------------------------------------------------------------------------
#define HP 36
#define AB_U32 (128 * HP)          // 4608 uint32 per matrix per stage
#define STAGE_U32 (2 * AB_U32)     // 9216
#define GT_SMEM_BYTES (2 * STAGE_U32 * 4)   // 73728

__device__ __forceinline__ void gt_issue(uint32_t sb, int stage, int kc,
                                         const __half* __restrict__ Ap,
                                         const __half* __restrict__ Bp, int t) {
    const int k0 = kc * 64;
    const uint32_t abase = sb + (uint32_t)(stage * STAGE_U32) * 4;
    const uint32_t bbase = abase + AB_U32 * 4;
#pragma unroll
    for (int r = 0; r < 4; r++) {
        const int idx = t + 256 * r;
        const int row = idx >> 3, j = idx & 7;
        CP_ASYNC16(abase + (uint32_t)(row * HP + 4 * j) * 4,
                   Ap + (size_t)row * 512 + k0 + 8 * j);
    }
#pragma unroll
    for (int r = 0; r < 4; r++) {
        const int idx = t + 256 * r;
        const int row = idx >> 3, j = idx & 7;
        CP_ASYNC16(bbase + (uint32_t)(row * HP + 4 * j) * 4,
                   Bp + (size_t)row * 512 + k0 + 8 * j);
    }
    CP_COMMIT();
}

template <int MODE>
__global__ void __launch_bounds__(256)
gemm_h(const float* __restrict__ bias) {
    extern __shared__ uint32_t smu[];
    const uint32_t sb = smem_u32(smu);
    const int t = threadIdx.x, warp = t >> 5, lane = t & 31;
    const int g = lane >> 2, tg = lane & 3;
    const int wm = (warp >> 2) * 64, wn = (warp & 3) * 32;
    const int bx = blockIdx.x, by = blockIdx.y;

    const __half* Ap =
        ((MODE == 0) ? g_imgth : (MODE == 3) ? g_attnh : g_audh) +
        (size_t)by * 128 * 512;
    const __half* Bp = g_wth + (size_t)MODE * 512 * 512 + (size_t)bx * 128 * 512;

    float acc[4][4][4];
#pragma unroll
    for (int mi = 0; mi < 4; mi++)
#pragma unroll
        for (int ni = 0; ni < 4; ni++)
#pragma unroll
            for (int j = 0; j < 4; j++) acc[mi][ni][j] = 0.f;

    gt_issue(sb, 0, 0, Ap, Bp, t);

#pragma unroll 1
    for (int c = 0; c < 8; c++) {
        if (c + 1 < 8) {
            gt_issue(sb, (c + 1) & 1, c + 1, Ap, Bp, t);
            CP_WAIT(1);
        } else {
            CP_WAIT(0);
        }
        __syncthreads();

        const uint32_t* As = smu + (c & 1) * STAGE_U32;
        const uint32_t* Bs = As + AB_U32;
#pragma unroll
        for (int ks = 0; ks < 4; ks++) {
            const int hk = ks * 8 + tg;
            uint32_t a[4][4], b[4][2];
#pragma unroll
            for (int ni = 0; ni < 4; ni++) {
                const uint32_t* br = Bs + (wn + ni * 8 + g) * HP;
                b[ni][0] = br[hk];
                b[ni][1] = br[hk + 4];
            }
#pragma unroll
            for (int mi = 0; mi < 4; mi++) {
                const uint32_t* ar0 = As + (wm + mi * 16 + g) * HP;
                const uint32_t* ar1 = ar0 + 8 * HP;
                a[mi][0] = ar0[hk];
                a[mi][1] = ar1[hk];
                a[mi][2] = ar0[hk + 4];
                a[mi][3] = ar1[hk + 4];
            }
#pragma unroll
            for (int mi = 0; mi < 4; mi++)
#pragma unroll
                for (int ni = 0; ni < 4; ni++)
                    mma_f16(acc[mi][ni], a[mi], b[ni]);
        }
        __syncthreads();
    }

    // epilogue
    const int rowbase = by * 128;
#pragma unroll
    for (int ni = 0; ni < 4; ni++) {
        const int cb = bx * 128 + wn + ni * 8 + 2 * tg;
        const float2 bv = *(const float2*)&bias[cb];
#pragma unroll
        for (int mi = 0; mi < 4; mi++) {
            const int r0 = rowbase + wm + mi * 16 + g;
            if (MODE == 3) {
                float2 o0, o1;
                o0.x = acc[mi][ni][0] + bv.x; o0.y = acc[mi][ni][1] + bv.y;
                o1.x = acc[mi][ni][2] + bv.x; o1.y = acc[mi][ni][3] + bv.y;
                *(float2*)&g_y[(size_t)r0 * 512 + cb] = o0;
                *(float2*)&g_y[(size_t)(r0 + 8) * 512 + cb] = o1;
            } else {
                __half* C = (MODE == 0) ? g_qh : (MODE == 1) ? g_kh : g_vh;
                const __half2 h0 =
                    __floats2half2_rn(acc[mi][ni][0] + bv.x, acc[mi][ni][1] + bv.y);
                const __half2 h1 =
                    __floats2half2_rn(acc[mi][ni][2] + bv.x, acc[mi][ni][3] + bv.y);
                *(__half2*)&C[(size_t)r0 * 512 + cb] = h0;
                *(__half2*)&C[(size_t)(r0 + 8) * 512 + cb] = h1;
            }
        }
    }
}

// ---------------------------------------------------------------------------
// Tensor-core attention (all fp16 inputs, fp32 accum/softmax):
// block = (b,h) x 128 q-rows, 256 threads, 8 warps, 16 q-rows/warp.
//   S = Q K^T : fp16 m16n8k16
//   softmax   : fp32 regs, quad shfl
//   O = P V   : fp16 m16n8k16, S-fragment packs directly into A-fragment
// smem (half2 units): Qs[128][36], Ks[256][36], V2[128][72] = 92,160 B
// ---------------------------------------------------------------------------
#define QS_OFF 0
#define KS_OFF (128 * 36)
#define V2_OFF (KS_OFF + 256 * 36)
#define ATTN_SMEM_BYTES ((V2_OFF + 128 * 72) * 4)

__global__ void __launch_bounds__(256, 1) attn_tc() {
    extern __shared__ uint32_t smu[];
    uint32_t* Qs = smu + QS_OFF;
    uint32_t* Ks = smu + KS_OFF;
    __half2* V2 = (__half2*)(smu + V2_OFF);

    const int b = blockIdx.x >> 3, h = blockIdx.x & 7;
    const int q0 = blockIdx.y << 7;
    const int t = threadIdx.x, warp = t >> 5, lane = t & 31;
    const int g = lane >> 2, tg = lane & 3;

    const __half* qb = g_qh + (size_t)(b * HW + q0) * CA + h * 64;
    const __half* kb = g_kh + (size_t)b * (KL * CA) + h * 64;
    const __half* vb = g_vh + (size_t)b * (KL * CA) + h * 64;

#pragma unroll
    for (int r = 0; r < 4; r++) {        // Q: 128 rows x 8 xfers
        const int idx = t + 256 * r;
        const int row = idx >> 3, j = idx & 7;
        *(uint4*)&Qs[row * 36 + 4 * j] =
            *(const uint4*)(qb + (size_t)row * CA + 8 * j);
    }
#pragma unroll
    for (int r = 0; r < 8; r++) {        // K: 256 rows x 8 xfers
        const int idx = t + 256 * r;
        const int row = idx >> 3, j = idx & 7;
        *(uint4*)&Ks[row * 36 + 4 * j] =
            *(const uint4*)(kb + (size_t)row * CA + 8 * j);
    }
#pragma unroll
    for (int r = 0; r < 16; r++) {       // V -> half2 key-pairs
        const int idx = t + 256 * r;
        const int kp = idx >> 5, d2 = idx & 31;
        const __half2 a = *(const __half2*)(vb + (size_t)(2 * kp) * CA + 2 * d2);
        const __half2 c = *(const __half2*)(vb + (size_t)(2 * kp + 1) * CA + 2 * d2);
        V2[kp * 72 + 2 * d2] = __halves2half2(__low2half(a), __low2half(c));
        V2[kp * 72 + 2 * d2 + 1] = __halves2half2(__high2half(a), __high2half(c));
    }
    __syncthreads();

    // Q fragments (4 k16-steps over d=64)
    uint32_t qf[4][4];
    const uint32_t* qw = Qs + warp * 16 * 36;
#pragma unroll
    for (int kc = 0; kc < 4; kc++) {
        const int hk = kc * 8 + tg;
        qf[kc][0] = qw[g * 36 + hk];
        qf[kc][1] = qw[(g + 8) * 36 + hk];
        qf[kc][2] = qw[g * 36 + hk + 4];
        qf[kc][3] = qw[(g + 8) * 36 + hk + 4];
    }

    // --- S = Q K^T ---
    float sc[32][4];
#pragma unroll
    for (int j = 0; j < 32; j++)
#pragma unroll
        for (int i = 0; i < 4; i++) sc[j][i] = 0.f;

#pragma unroll
    for (int j = 0; j < 32; j++) {       // key octet j
        const uint32_t* kr = Ks + (j * 8 + g) * 36;
#pragma unroll
        for (int kc = 0; kc < 4; kc++) {
            uint32_t bf[2];
            bf[0] = kr[kc * 8 + tg];
            bf[1] = kr[kc * 8 + tg + 4];
            mma_f16(sc[j], qf[kc], bf);
        }
    }

    // --- softmax (rows g, g+8; scale = 0.125) ---
    uint32_t pl[32], ph[32];
    {
        float m0 = -1e30f, m1 = -1e30f;
#pragma unroll
        for (int j = 0; j < 32; j++) {
            m0 = fmaxf(m0, fmaxf(sc[j][0], sc[j][1]));
            m1 = fmaxf(m1, fmaxf(sc[j][2], sc[j][3]));
        }
        m0 = fmaxf(m0, __shfl_xor_sync(0xffffffffu, m0, 1));
        m0 = fmaxf(m0, __shfl_xor_sync(0xffffffffu, m0, 2));
        m1 = fmaxf(m1, __shfl_xor_sync(0xffffffffu, m1, 1));
        m1 = fmaxf(m1, __shfl_xor_sync(0xffffffffu, m1, 2));
        float s0 = 0.f, s1 = 0.f;
#pragma unroll
        for (int j = 0; j < 32; j++) {
            sc[j][0] = __expf(0.125f * (sc[j][0] - m0));
            sc[j][1] = __expf(0.125f * (sc[j][1] - m0));
            sc[j][2] = __expf(0.125f * (sc[j][2] - m1));
            sc[j][3] = __expf(0.125f * (sc[j][3] - m1));
            s0 += sc[j][0] + sc[j][1];
            s1 += sc[j][2] + sc[j][3];
        }
        s0 += __shfl_xor_sync(0xffffffffu, s0, 1);
        s0 += __shfl_xor_sync(0xffffffffu, s0, 2);
        s1 += __shfl_xor_sync(0xffffffffu, s1, 1);
        s1 += __shfl_xor_sync(0xffffffffu, s1, 2);
        const float i0 = __frcp_rn(s0), i1 = __frcp_rn(s1);
#pragma unroll
        for (int j = 0; j < 32; j++) {
            const __half2 lo = __floats2half2_rn(sc[j][0] * i0, sc[j][1] * i0);
            const __half2 hi = __floats2half2_rn(sc[j][2] * i1, sc[j][3] * i1);
            pl[j] = *(const uint32_t*)&lo;
            ph[j] = *(const uint32_t*)&hi;
        }
    }

    // --- O = P V ---
    float oc[8][4];
#pragma unroll
    for (int ni = 0; ni < 8; ni++)
#pragma unroll
        for (int i = 0; i < 4; i++) oc[ni][i] = 0.f;

#pragma unroll
    for (int kc = 0; kc < 16; kc++) {
        uint32_t a[4];
        a[0] = pl[2 * kc];
        a[1] = ph[2 * kc];
        a[2] = pl[2 * kc + 1];
        a[3] = ph[2 * kc + 1];
        const __half2* vr0 = V2 + (kc * 8 + tg) * 72;
        const __half2* vr1 = V2 + (kc * 8 + tg + 4) * 72;
#pragma unroll
        for (int ni = 0; ni < 8; ni++) {
            uint32_t bf[2];
            bf[0] = *(const uint32_t*)&vr0[ni * 8 + g];
            bf[1] = *(const uint32_t*)&vr1[ni * 8 + g];
            mma_f16(oc[ni], a, bf);
        }
    }

    __half* ob = g_attnh + (size_t)(b * HW + q0 + warp * 16) * CA + h * 64;
#pragma unroll
    for (int ni = 0; ni < 8; ni++) {
        const int col = ni * 8 + 2 * tg;
        *(__half2*)&ob[(size_t)g * CA + col] =
            __floats2half2_rn(oc[ni][0], oc[ni][1]);
        *(__half2*)&ob[(size_t)(g + 8) * CA + col] =
            __floats2half2_rn(oc[ni][2], oc[ni][3]);
    }
}

// ---------------------------------------------------------------------------
// Residual + LayerNorm + transpose to [b, c, h, w].
// ---------------------------------------------------------------------------
#define LN_SMEM_BYTES (32 * 513 * 4)

__global__ void __launch_bounds__(256, 1)
ln_kernel(const float* __restrict__ img, const float* __restrict__ gamma,
          const float* __restrict__ beta, float* __restrict__ out) {
    extern __shared__ float sm[];   // [32][513]
    __shared__ float smu2[32], srv[32];
    const int b = blockIdx.x >> 5;
    const int s0 = (blockIdx.x & 31) << 5;
    const int t = threadIdx.x;

#pragma unroll
    for (int r = 0; r < 16; r++) {
        const int u = t + 256 * r;
        const int s = u >> 7, c4 = (u & 127) << 2;
        const float4 v = *(const float4*)&g_y[((size_t)(b * HW + s0 + s)) * CI + c4];
        float* dst = sm + s * 513 + c4;
        dst[0] = v.x; dst[1] = v.y; dst[2] = v.z; dst[3] = v.w;
    }
    __syncthreads();
#pragma unroll 8
    for (int r = 0; r < 64; r++) {
        const int u = t + 256 * r;
        const int c = u >> 5, s = u & 31;
        sm[s * 513 + c] += img[(size_t)b * (CI * HW) + (size_t)c * HW + s0 + s];
    }
    __syncthreads();

    const int warp = t >> 5, lane = t & 31;
#pragma unroll
    for (int rr = 0; rr < 4; rr++) {
        const int s = warp * 4 + rr;
        const float* row = sm + s * 513;
        float sum = 0.f;
#pragma unroll
        for (int i = 0; i < 16; i++) sum += row[lane + 32 * i];
#pragma unroll
        for (int off = 16; off > 0; off >>= 1)
            sum += __shfl_xor_sync(0xffffffffu, sum, off);
        const float mu = sum * (1.0f / 512.0f);
        float var = 0.f;
#pragma unroll
        for (int i = 0; i < 16; i++) {
            const float d = row[lane + 32 * i] - mu;
            var += d * d;
        }
#pragma unroll
        for (int off = 16; off > 0; off >>= 1)
            var += __shfl_xor_sync(0xffffffffu, var, off);
        var *= (1.0f / 512.0f);
        if (lane == 0) { smu2[s] = mu; srv[s] = rsqrtf(var + 1e-5f); }
    }
    __syncthreads();

    const float mu = smu2[lane], rv = srv[lane];
#pragma unroll 4
    for (int ci = 0; ci < 64; ci++) {
        const int c = warp * 64 + ci;
        const float val = (sm[lane * 513 + c] - mu) * rv * gamma[c] + beta[c];
        out[(size_t)b * (CI * HW) + (size_t)c * HW + s0 + lane] = val;
    }
}

// ---------------------------------------------------------------------------
extern "C" void kernel_launch(void* const* d_in, const int* in_sizes, int n_in,
                              void* d_out, int out_size) {
    (void)in_sizes; (void)n_in; (void)out_size;
    const float* img   = (const float*)d_in[0];
    const float* aud   = (const float*)d_in[1];
    const float* Wq    = (const float*)d_in[2];
    const float* bq    = (const float*)d_in[3];
    const float* Wk    = (const float*)d_in[4];
    const float* bk    = (const float*)d_in[5];
    const float* Wv    = (const float*)d_in[6];
    const float* bv    = (const float*)d_in[7];
    const float* Wo    = (const float*)d_in[8];
    const float* bo    = (const float*)d_in[9];
    const float* gamma = (const float*)d_in[10];
    const float* beta  = (const float*)d_in[11];
    float* out = (float*)d_out;

    cudaFuncSetAttribute((const void*)gemm_h<0>,
                         cudaFuncAttributeMaxDynamicSharedMemorySize, GT_SMEM_BYTES);
    cudaFuncSetAttribute((const void*)gemm_h<1>,
                         cudaFuncAttributeMaxDynamicSharedMemorySize, GT_SMEM_BYTES);
    cudaFuncSetAttribute((const void*)gemm_h<2>,
                         cudaFuncAttributeMaxDynamicSharedMemorySize, GT_SMEM_BYTES);
    cudaFuncSetAttribute((const void*)gemm_h<3>,
                         cudaFuncAttributeMaxDynamicSharedMemorySize, GT_SMEM_BYTES);
    cudaFuncSetAttribute((const void*)attn_tc,
                         cudaFuncAttributeMaxDynamicSharedMemorySize, ATTN_SMEM_BYTES);
    cudaFuncSetAttribute((const void*)ln_kernel,
                         cudaFuncAttributeMaxDynamicSharedMemorySize, LN_SMEM_BYTES);

    // fp16 conversions (replace tf32 rounding; also fold in transposes)
    cvt_img_t<<<dim3(16, 32, 16), dim3(32, 8)>>>(img);
    cvt_aud<<<NB * KL * CA / 4 / 256, 256>>>((const float4*)aud);
    cvt_w_t<<<dim3(16, 16, 4), dim3(32, 8)>>>(Wq, Wk, Wv, Wo);

    gemm_h<0><<<dim3(4, 128), 256, GT_SMEM_BYTES>>>(bq);
    gemm_h<1><<<dim3(4, 32), 256, GT_SMEM_BYTES>>>(bk);
    gemm_h<2><<<dim3(4, 32), 256, GT_SMEM_BYTES>>>(bv);
    attn_tc<<<dim3(128, 8), 256, ATTN_SMEM_BYTES>>>();
    gemm_h<3><<<dim3(4, 128), 256, GT_SMEM_BYTES>>>(bo);
    ln_kernel<<<512, 256, LN_SMEM_BYTES>>>(img, gamma, beta, out);
}

// round 14
// speedup vs baseline: 1.0199x; 1.0199x over previous
#include <cuda_runtime.h>
#include <cuda_fp16.h>
#include <cstdint>

#define NB 16
#define HW 1024
#define CI 512
#define CA 512
#define KL 256

// Scratch (alloc-free: __device__ globals)
__device__ __half g_qh[NB * HW * CA];     // Q (half, from Q GEMM)
__device__ __half g_kh[NB * KL * CA];     // K
__device__ __half g_vh[NB * KL * CA];     // V
__device__ __half g_attnh[NB * HW * CA];  // attention out (half)
__device__ float  g_y[NB * HW * CI];      // O GEMM out (fp32, LN input)
__device__ __half g_imgth[NB * HW * CI];  // img transposed [b][s][c], half
__device__ __half g_audh[NB * KL * CA];   // audio, half
__device__ __half g_wth[4 * 512 * 512];   // weights transposed [n][k], half

// ---------------------------------------------------------------------------
// Helpers
// ---------------------------------------------------------------------------
__device__ __forceinline__ uint32_t smem_u32(const void* p) {
    uint32_t a;
    asm("{ .reg .u64 t; cvta.to.shared.u64 t, %1; cvt.u32.u64 %0, t; }"
        : "=r"(a) : "l"(p));
    return a;
}
#define CP_ASYNC16(dst, src) \
    asm volatile("cp.async.cg.shared.global [%0], [%1], 16;" \
                 :: "r"(dst), "l"(src) : "memory")
#define CP_COMMIT() asm volatile("cp.async.commit_group;" ::: "memory")
#define CP_WAIT(n)  asm volatile("cp.async.wait_group %0;" :: "n"(n) : "memory")

__device__ __forceinline__ void mma_f16(float (&c)[4], const uint32_t (&a)[4],
                                        const uint32_t (&b)[2]) {
    asm volatile(
        "mma.sync.aligned.m16n8k16.row.col.f32.f16.f16.f32 "
        "{%0,%1,%2,%3}, {%4,%5,%6,%7}, {%8,%9}, {%0,%1,%2,%3};"
        : "+f"(c[0]), "+f"(c[1]), "+f"(c[2]), "+f"(c[3])
        : "r"(a[0]), "r"(a[1]), "r"(a[2]), "r"(a[3]), "r"(b[0]), "r"(b[1]));
}
__device__ __forceinline__ void ldsm_x4(uint32_t (&r)[4], uint32_t addr) {
    asm volatile("ldmatrix.sync.aligned.m8n8.x4.shared.b16 {%0,%1,%2,%3}, [%4];"
                 : "=r"(r[0]), "=r"(r[1]), "=r"(r[2]), "=r"(r[3]) : "r"(addr));
}
__device__ __forceinline__ void ldsm_x2(uint32_t (&r)[2], uint32_t addr) {
    asm volatile("ldmatrix.sync.aligned.m8n8.x2.shared.b16 {%0,%1}, [%2];"
                 : "=r"(r[0]), "=r"(r[1]) : "r"(addr));
}

// ---------------------------------------------------------------------------
// Converters
// ---------------------------------------------------------------------------
// img [b][c][s] fp32 -> [b][s][c] half (transpose through smem)
__global__ void cvt_img_t(const float* __restrict__ img) {
    __shared__ float tile[32][33];
    const int c0 = blockIdx.x * 32, s0 = blockIdx.y * 32, b = blockIdx.z;
    const int tx = threadIdx.x, ty = threadIdx.y;
#pragma unroll
    for (int i = 0; i < 4; i++)
        tile[ty + 8 * i][tx] =
            img[((size_t)b * CI + c0 + ty + 8 * i) * HW + s0 + tx];
    __syncthreads();
#pragma unroll
    for (int i = 0; i < 4; i++)
        g_imgth[((size_t)b * HW + s0 + ty + 8 * i) * CI + c0 + tx] =
            __float2half(tile[tx][ty + 8 * i]);
}

// W [k][n] fp32 -> g_wth[z][n][k] half (transpose)
__global__ void cvt_w_t(const float* __restrict__ W0,
                        const float* __restrict__ W1,
                        const float* __restrict__ W2,
                        const float* __restrict__ W3) {
    __shared__ float tile[32][33];
    const int z = blockIdx.z;
    const float* W = (z == 0) ? W0 : (z == 1) ? W1 : (z == 2) ? W2 : W3;
    __half* T = g_wth + (size_t)z * 512 * 512;
    const int n0 = blockIdx.x * 32, k0 = blockIdx.y * 32;
    const int tx = threadIdx.x, ty = threadIdx.y;
#pragma unroll
    for (int i = 0; i < 4; i++)
        tile[ty + 8 * i][tx] = W[(size_t)(k0 + ty + 8 * i) * 512 + n0 + tx];
    __syncthreads();
#pragma unroll
    for (int i = 0; i < 4; i++)
        T[(size_t)(n0 + ty + 8 * i) * 512 + k0 + tx] = __float2half(tile[tx][ty + 8 * i]);
}

// audio fp32 -> half, elementwise
__global__ void cvt_aud(const float4* __restrict__ src) {
    const int i = blockIdx.x * blockDim.x + threadIdx.x;
    const float4 v = src[i];
    __half2* dst = (__half2*)g_audh;
    dst[2 * i] = __floats2half2_rn(v.x, v.y);
    dst[2 * i + 1] = __floats2half2_rn(v.z, v.w);
}

// ---------------------------------------------------------------------------
// HGEMM: C[M,512] = A[M,512] @ Wt^T + bias   (A row-major half, Wt [n][k] half)
// 128x128 tile, BK=64, 256 threads (8 warps 2m x 4n), warp tile 64x32,
// m16n8k16 fp16 MMA fp32 accum, 3-stage cp.async, ldmatrix fragment loads.
// smem row pitch = 36 u32 = 144 B: ldmatrix 8-row phases hit disjoint 16B
// slots (144*i mod 128 all distinct) -> conflict-free.
// MODE 0: A=g_imgth -> g_qh    MODE 1 (z=0/1): g_audh -> g_kh / g_vh
// MODE 3: A=g_attnh -> g_y (fp32)
// ---------------------------------------------------------------------------
#define HP 36
#define AB_U32 (128 * HP)            // 4608 u32 per matrix per stage
#define STAGE_U32 (2 * AB_U32)       // 9216
#define STAGE_B (STAGE_U32 * 4)      // 36864
#define GT_SMEM_BYTES (3 * STAGE_B)  // 110592

__device__ __forceinline__ void gt_issue(uint32_t sb, int stage, int kc,
                                         const __half* __restrict__ Ap,
                                         const __half* __restrict__ Bp, int t) {
    const int k0 = kc * 64;
    const uint32_t abase = sb + (uint32_t)stage * STAGE_B;
    const uint32_t bbase = abase + AB_U32 * 4;
#pragma unroll
    for (int r = 0; r < 4; r++) {
        const int idx = t + 256 * r;
        const int row = idx >> 3, j = idx & 7;
        CP_ASYNC16(abase + (uint32_t)(row * HP + 4 * j) * 4,
                   Ap + (size_t)row * 512 + k0 + 8 * j);
    }
#pragma unroll
    for (int r = 0; r < 4; r++) {
        const int idx = t + 256 * r;
        const int row = idx >> 3, j = idx & 7;
        CP_ASYNC16(bbase + (uint32_t)(row * HP + 4 * j) * 4,
                   Bp + (size_t)row * 512 + k0 + 8 * j);
    }
    CP_COMMIT();
}

template <int MODE>
__global__ void __launch_bounds__(256)
gemm_h(const float* __restrict__ bias, const float* __restrict__ bias2) {
    extern __shared__ uint32_t smu[];
    const uint32_t sb = smem_u32(smu);
    const int t = threadIdx.x, warp = t >> 5, lane = t & 31;
    const int g = lane >> 2, tg = lane & 3;
    const int wm = (warp >> 2) * 64, wn = (warp & 3) * 32;
    const int bx = blockIdx.x, by = blockIdx.y;
    const int z = (MODE == 1) ? blockIdx.z : 0;
    if (MODE == 1 && z) bias = bias2;

    const __half* Ap =
        ((MODE == 0) ? g_imgth : (MODE == 3) ? g_attnh : g_audh) +
        (size_t)by * 128 * 512;
    const int wsel = (MODE == 1) ? (1 + z) : MODE;
    const __half* Bp = g_wth + (size_t)wsel * 512 * 512 + (size_t)bx * 128 * 512;

    float acc[4][4][4];
#pragma unroll
    for (int mi = 0; mi < 4; mi++)
#pragma unroll
        for (int ni = 0; ni < 4; ni++)
#pragma unroll
            for (int j = 0; j < 4; j++) acc[mi][ni][j] = 0.f;

    // per-lane ldmatrix byte offsets (within a stage)
    uint32_t a_off[4], b_off[4];
#pragma unroll
    for (int mi = 0; mi < 4; mi++)
        a_off[mi] = (uint32_t)(wm + mi * 16 + (lane & 15)) * 144 +
                    (uint32_t)(lane >> 4) * 16;
#pragma unroll
    for (int ni = 0; ni < 4; ni++)
        b_off[ni] = AB_U32 * 4 +
                    (uint32_t)(wn + ni * 8 + (lane & 7)) * 144 +
                    (uint32_t)((lane >> 3) & 1) * 16;

    gt_issue(sb, 0, 0, Ap, Bp, t);
    gt_issue(sb, 1, 1, Ap, Bp, t);

#pragma unroll 1
    for (int c = 0; c < 8; c++) {
        if (c + 2 < 8) {
            gt_issue(sb, (c + 2) % 3, c + 2, Ap, Bp, t);
            CP_WAIT(2);
        } else if (c == 6) {
            CP_WAIT(1);
        } else {
            CP_WAIT(0);
        }
        __syncthreads();

        const uint32_t stb = sb + (uint32_t)(c % 3) * STAGE_B;
#pragma unroll
        for (int ks = 0; ks < 4; ks++) {
            const uint32_t ko = (uint32_t)ks * 32;
            uint32_t a[4][4], b[4][2];
#pragma unroll
            for (int mi = 0; mi < 4; mi++) ldsm_x4(a[mi], stb + a_off[mi] + ko);
#pragma unroll
            for (int ni = 0; ni < 4; ni++) ldsm_x2(b[ni], stb + b_off[ni] + ko);
#pragma unroll
            for (int mi = 0; mi < 4; mi++)
#pragma unroll
                for (int ni = 0; ni < 4; ni++)
                    mma_f16(acc[mi][ni], a[mi], b[ni]);
        }
        __syncthreads();
    }

    // epilogue
    const int rowbase = by * 128;
#pragma unroll
    for (int ni = 0; ni < 4; ni++) {
        const int cb = bx * 128 + wn + ni * 8 + 2 * tg;
        const float2 bv = *(const float2*)&bias[cb];
#pragma unroll
        for (int mi = 0; mi < 4; mi++) {
            const int r0 = rowbase + wm + mi * 16 + g;
            if (MODE == 3) {
                float2 o0, o1;
                o0.x = acc[mi][ni][0] + bv.x; o0.y = acc[mi][ni][1] + bv.y;
                o1.x = acc[mi][ni][2] + bv.x; o1.y = acc[mi][ni][3] + bv.y;
                *(float2*)&g_y[(size_t)r0 * 512 + cb] = o0;
                *(float2*)&g_y[(size_t)(r0 + 8) * 512 + cb] = o1;
            } else {
                __half* C = (MODE == 0) ? g_qh : (z == 0) ? g_kh : g_vh;
                const __half2 h0 =
                    __floats2half2_rn(acc[mi][ni][0] + bv.x, acc[mi][ni][1] + bv.y);
                const __half2 h1 =
                    __floats2half2_rn(acc[mi][ni][2] + bv.x, acc[mi][ni][3] + bv.y);
                *(__half2*)&C[(size_t)r0 * 512 + cb] = h0;
                *(__half2*)&C[(size_t)(r0 + 8) * 512 + cb] = h1;
            }
        }
    }
}

// ---------------------------------------------------------------------------
// Tensor-core attention (all fp16 inputs, fp32 accum/softmax):
// block = (b,h) x 128 q-rows, 256 threads, 8 warps, 16 q-rows/warp.
// ---------------------------------------------------------------------------
#define QS_OFF 0
#define KS_OFF (128 * 36)
#define V2_OFF (KS_OFF + 256 * 36)
#define ATTN_SMEM_BYTES ((V2_OFF + 128 * 72) * 4)

__global__ void __launch_bounds__(256, 1) attn_tc() {
    extern __shared__ uint32_t smu[];
    uint32_t* Qs = smu + QS_OFF;
    uint32_t* Ks = smu + KS_OFF;
    __half2* V2 = (__half2*)(smu + V2_OFF);

    const int b = blockIdx.x >> 3, h = blockIdx.x & 7;
    const int q0 = blockIdx.y << 7;
    const int t = threadIdx.x, warp = t >> 5, lane = t & 31;
    const int g = lane >> 2, tg = lane & 3;

    const __half* qb = g_qh + (size_t)(b * HW + q0) * CA + h * 64;
    const __half* kb = g_kh + (size_t)b * (KL * CA) + h * 64;
    const __half* vb = g_vh + (size_t)b * (KL * CA) + h * 64;

#pragma unroll
    for (int r = 0; r < 4; r++) {        // Q: 128 rows x 8 xfers
        const int idx = t + 256 * r;
        const int row = idx >> 3, j = idx & 7;
        *(uint4*)&Qs[row * 36 + 4 * j] =
            *(const uint4*)(qb + (size_t)row * CA + 8 * j);
    }
#pragma unroll
    for (int r = 0; r < 8; r++) {        // K: 256 rows x 8 xfers
        const int idx = t + 256 * r;
        const int row = idx >> 3, j = idx & 7;
        *(uint4*)&Ks[row * 36 + 4 * j] =
            *(const uint4*)(kb + (size_t)row * CA + 8 * j);
    }
#pragma unroll
    for (int r = 0; r < 16; r++) {       // V -> half2 key-pairs
        const int idx = t + 256 * r;
        const int kp = idx >> 5, d2 = idx & 31;
        const __half2 a = *(const __half2*)(vb + (size_t)(2 * kp) * CA + 2 * d2);
        const __half2 c = *(const __half2*)(vb + (size_t)(2 * kp + 1) * CA + 2 * d2);
        V2[kp * 72 + 2 * d2] = __halves2half2(__low2half(a), __low2half(c));
        V2[kp * 72 + 2 * d2 + 1] = __halves2half2(__high2half(a), __high2half(c));
    }
    __syncthreads();

    // Q fragments (4 k16-steps over d=64)
    uint32_t qf[4][4];
    const uint32_t* qw = Qs + warp * 16 * 36;
#pragma unroll
    for (int kc = 0; kc < 4; kc++) {
        const int hk = kc * 8 + tg;
        qf[kc][0] = qw[g * 36 + hk];
        qf[kc][1] = qw[(g + 8) * 36 + hk];
        qf[kc][2] = qw[g * 36 + hk + 4];
        qf[kc][3] = qw[(g + 8) * 36 + hk + 4];
    }

    // --- S = Q K^T ---
    float sc[32][4];
#pragma unroll
    for (int j = 0; j < 32; j++)
#pragma unroll
        for (int i = 0; i < 4; i++) sc[j][i] = 0.f;

#pragma unroll
    for (int j = 0; j < 32; j++) {       // key octet j
        const uint32_t* kr = Ks + (j * 8 + g) * 36;
#pragma unroll
        for (int kc = 0; kc < 4; kc++) {
            uint32_t bf[2];
            bf[0] = kr[kc * 8 + tg];
            bf[1] = kr[kc * 8 + tg + 4];
            mma_f16(sc[j], qf[kc], bf);
        }
    }

    // --- softmax (rows g, g+8; scale = 0.125) ---
    uint32_t pl[32], ph[32];
    {
        float m0 = -1e30f, m1 = -1e30f;
#pragma unroll
        for (int j = 0; j < 32; j++) {
            m0 = fmaxf(m0, fmaxf(sc[j][0], sc[j][1]));
            m1 = fmaxf(m1, fmaxf(sc[j][2], sc[j][3]));
        }
        m0 = fmaxf(m0, __shfl_xor_sync(0xffffffffu, m0, 1));
        m0 = fmaxf(m0, __shfl_xor_sync(0xffffffffu, m0, 2));
        m1 = fmaxf(m1, __shfl_xor_sync(0xffffffffu, m1, 1));
        m1 = fmaxf(m1, __shfl_xor_sync(0xffffffffu, m1, 2));
        float s0 = 0.f, s1 = 0.f;
#pragma unroll
        for (int j = 0; j < 32; j++) {
            sc[j][0] = __expf(0.125f * (sc[j][0] - m0));
            sc[j][1] = __expf(0.125f * (sc[j][1] - m0));
            sc[j][2] = __expf(0.125f * (sc[j][2] - m1));
            sc[j][3] = __expf(0.125f * (sc[j][3] - m1));
            s0 += sc[j][0] + sc[j][1];
            s1 += sc[j][2] + sc[j][3];
        }
        s0 += __shfl_xor_sync(0xffffffffu, s0, 1);
        s0 += __shfl_xor_sync(0xffffffffu, s0, 2);
        s1 += __shfl_xor_sync(0xffffffffu, s1, 1);
        s1 += __shfl_xor_sync(0xffffffffu, s1, 2);
        const float i0 = __frcp_rn(s0), i1 = __frcp_rn(s1);
#pragma unroll
        for (int j = 0; j < 32; j++) {
            const __half2 lo = __floats2half2_rn(sc[j][0] * i0, sc[j][1] * i0);
            const __half2 hi = __floats2half2_rn(sc[j][2] * i1, sc[j][3] * i1);
            pl[j] = *(const uint32_t*)&lo;
            ph[j] = *(const uint32_t*)&hi;
        }
    }

    // --- O = P V ---
    float oc[8][4];
#pragma unroll
    for (int ni = 0; ni < 8; ni++)
#pragma unroll
        for (int i = 0; i < 4; i++) oc[ni][i] = 0.f;

#pragma unroll
    for (int kc = 0; kc < 16; kc++) {
        uint32_t a[4];
        a[0] = pl[2 * kc];
        a[1] = ph[2 * kc];
        a[2] = pl[2 * kc + 1];
        a[3] = ph[2 * kc + 1];
        const __half2* vr0 = V2 + (kc * 8 + tg) * 72;
        const __half2* vr1 = V2 + (kc * 8 + tg + 4) * 72;
#pragma unroll
        for (int ni = 0; ni < 8; ni++) {
            uint32_t bf[2];
            bf[0] = *(const uint32_t*)&vr0[ni * 8 + g];
            bf[1] = *(const uint32_t*)&vr1[ni * 8 + g];
            mma_f16(oc[ni], a, bf);
        }
    }

    __half* ob = g_attnh + (size_t)(b * HW + q0 + warp * 16) * CA + h * 64;
#pragma unroll
    for (int ni = 0; ni < 8; ni++) {
        const int col = ni * 8 + 2 * tg;
        *(__half2*)&ob[(size_t)g * CA + col] =
            __floats2half2_rn(oc[ni][0], oc[ni][1]);
        *(__half2*)&ob[(size_t)(g + 8) * CA + col] =
            __floats2half2_rn(oc[ni][2], oc[ni][3]);
    }
}

// ---------------------------------------------------------------------------
// Residual + LayerNorm + transpose to [b, c, h, w].
// ---------------------------------------------------------------------------
#define LN_SMEM_BYTES (32 * 513 * 4)

__global__ void __launch_bounds__(256, 1)
ln_kernel(const float* __restrict__ img, const float* __restrict__ gamma,
          const float* __restrict__ beta, float* __restrict__ out) {
    extern __shared__ float sm[];   // [32][513]
    __shared__ float smu2[32], srv[32];
    const int b = blockIdx.x >> 5;
    const int s0 = (blockIdx.x & 31) << 5;
    const int t = threadIdx.x;

#pragma unroll
    for (int r = 0; r < 16; r++) {
        const int u = t + 256 * r;
        const int s = u >> 7, c4 = (u & 127) << 2;
        const float4 v = *(const float4*)&g_y[((size_t)(b * HW + s0 + s)) * CI + c4];
        float* dst = sm + s * 513 + c4;
        dst[0] = v.x; dst[1] = v.y; dst[2] = v.z; dst[3] = v.w;
    }
    __syncthreads();
#pragma unroll 8
    for (int r = 0; r < 64; r++) {
        const int u = t + 256 * r;
        const int c = u >> 5, s = u & 31;
        sm[s * 513 + c] += img[(size_t)b * (CI * HW) + (size_t)c * HW + s0 + s];
    }
    __syncthreads();

    const int warp = t >> 5, lane = t & 31;
#pragma unroll
    for (int rr = 0; rr < 4; rr++) {
        const int s = warp * 4 + rr;
        const float* row = sm + s * 513;
        float sum = 0.f;
#pragma unroll
        for (int i = 0; i < 16; i++) sum += row[lane + 32 * i];
#pragma unroll
        for (int off = 16; off > 0; off >>= 1)
            sum += __shfl_xor_sync(0xffffffffu, sum, off);
        const float mu = sum * (1.0f / 512.0f);
        float var = 0.f;
#pragma unroll
        for (int i = 0; i < 16; i++) {
            const float d = row[lane + 32 * i] - mu;
            var += d * d;
        }
#pragma unroll
        for (int off = 16; off > 0; off >>= 1)
            var += __shfl_xor_sync(0xffffffffu, var, off);
        var *= (1.0f / 512.0f);
        if (lane == 0) { smu2[s] = mu; srv[s] = rsqrtf(var + 1e-5f); }
    }
    __syncthreads();

    const float mu = smu2[lane], rv = srv[lane];
#pragma unroll 4
    for (int ci = 0; ci < 64; ci++) {
        const int c = warp * 64 + ci;
        const float val = (sm[lane * 513 + c] - mu) * rv * gamma[c] + beta[c];
        out[(size_t)b * (CI * HW) + (size_t)c * HW + s0 + lane] = val;
    }
}

// ---------------------------------------------------------------------------
extern "C" void kernel_launch(void* const* d_in, const int* in_sizes, int n_in,
                              void* d_out, int out_size) {
    (void)in_sizes; (void)n_in; (void)out_size;
    const float* img   = (const float*)d_in[0];
    const float* aud   = (const float*)d_in[1];
    const float* Wq    = (const float*)d_in[2];
    const float* bq    = (const float*)d_in[3];
    const float* Wk    = (const float*)d_in[4];
    const float* bk    = (const float*)d_in[5];
    const float* Wv    = (const float*)d_in[6];
    const float* bv    = (const float*)d_in[7];
    const float* Wo    = (const float*)d_in[8];
    const float* bo    = (const float*)d_in[9];
    const float* gamma = (const float*)d_in[10];
    const float* beta  = (const float*)d_in[11];
    float* out = (float*)d_out;

    cudaFuncSetAttribute((const void*)gemm_h<0>,
                         cudaFuncAttributeMaxDynamicSharedMemorySize, GT_SMEM_BYTES);
    cudaFuncSetAttribute((const void*)gemm_h<1>,
                         cudaFuncAttributeMaxDynamicSharedMemorySize, GT_SMEM_BYTES);
    cudaFuncSetAttribute((const void*)gemm_h<3>,
                         cudaFuncAttributeMaxDynamicSharedMemorySize, GT_SMEM_BYTES);
    cudaFuncSetAttribute((const void*)attn_tc,
                         cudaFuncAttributeMaxDynamicSharedMemorySize, ATTN_SMEM_BYTES);
    cudaFuncSetAttribute((const void*)ln_kernel,
                         cudaFuncAttributeMaxDynamicSharedMemorySize, LN_SMEM_BYTES);

    // fp16 conversions (fold in transposes)
    cvt_img_t<<<dim3(16, 32, 16), dim3(32, 8)>>>(img);
    cvt_aud<<<NB * KL * CA / 4 / 256, 256>>>((const float4*)aud);
    cvt_w_t<<<dim3(16, 16, 4), dim3(32, 8)>>>(Wq, Wk, Wv, Wo);

    gemm_h<0><<<dim3(4, 128), 256, GT_SMEM_BYTES>>>(bq, nullptr);
    gemm_h<1><<<dim3(4, 32, 2), 256, GT_SMEM_BYTES>>>(bk, bv);   // K (z=0) + V (z=1)
    attn_tc<<<dim3(128, 8), 256, ATTN_SMEM_BYTES>>>();
    gemm_h<3><<<dim3(4, 128), 256, GT_SMEM_BYTES>>>(bo, nullptr);
    ln_kernel<<<512, 256, LN_SMEM_BYTES>>>(img, gamma, beta, out);
}

// round 17
// speedup vs baseline: 1.0572x; 1.0366x over previous
#include <cuda_runtime.h>
#include <cuda_fp16.h>
#include <cstdint>

#define NB 16
#define HW 1024
#define CI 512
#define CA 512
#define KL 256

// Scratch (alloc-free: __device__ globals)
__device__ __half g_qh[NB * HW * CA];     // Q (half, from Q GEMM)
__device__ __half g_kh[NB * KL * CA];     // K
__device__ __half g_vh[NB * KL * CA];     // V
__device__ __half g_attnh[NB * HW * CA];  // attention out (half)
__device__ float  g_y[NB * HW * CI];      // O GEMM out (fp32, LN input)
__device__ __half g_imgth[NB * HW * CI];  // img transposed [b][s][c], half
__device__ __half g_audh[NB * KL * CA];   // audio, half
__device__ __half g_wth[4 * 512 * 512];   // weights transposed [n][k], half

// ---------------------------------------------------------------------------
// Helpers
// ---------------------------------------------------------------------------
__device__ __forceinline__ uint32_t smem_u32(const void* p) {
    uint32_t a;
    asm("{ .reg .u64 t; cvta.to.shared.u64 t, %1; cvt.u32.u64 %0, t; }"
        : "=r"(a) : "l"(p));
    return a;
}
#define CP_ASYNC16(dst, src) \
    asm volatile("cp.async.cg.shared.global [%0], [%1], 16;" \
                 :: "r"(dst), "l"(src) : "memory")
#define CP_COMMIT() asm volatile("cp.async.commit_group;" ::: "memory")
#define CP_WAIT(n)  asm volatile("cp.async.wait_group %0;" :: "n"(n) : "memory")

__device__ __forceinline__ void mma_f16(float (&c)[4], const uint32_t (&a)[4],
                                        const uint32_t (&b)[2]) {
    asm volatile(
        "mma.sync.aligned.m16n8k16.row.col.f32.f16.f16.f32 "
        "{%0,%1,%2,%3}, {%4,%5,%6,%7}, {%8,%9}, {%0,%1,%2,%3};"
        : "+f"(c[0]), "+f"(c[1]), "+f"(c[2]), "+f"(c[3])
        : "r"(a[0]), "r"(a[1]), "r"(a[2]), "r"(a[3]), "r"(b[0]), "r"(b[1]));
}
__device__ __forceinline__ void ldsm_x4(uint32_t (&r)[4], uint32_t addr) {
    asm volatile("ldmatrix.sync.aligned.m8n8.x4.shared.b16 {%0,%1,%2,%3}, [%4];"
                 : "=r"(r[0]), "=r"(r[1]), "=r"(r[2]), "=r"(r[3]) : "r"(addr));
}
__device__ __forceinline__ void ldsm_x2(uint32_t (&r)[2], uint32_t addr) {
    asm volatile("ldmatrix.sync.aligned.m8n8.x2.shared.b16 {%0,%1}, [%2];"
                 : "=r"(r[0]), "=r"(r[1]) : "r"(addr));
}

// ---------------------------------------------------------------------------
// Converters
// ---------------------------------------------------------------------------
// img [b][c][s] fp32 -> [b][s][c] half (transpose through smem)
__global__ void cvt_img_t(const float* __restrict__ img) {
    __shared__ float tile[32][33];
    const int c0 = blockIdx.x * 32, s0 = blockIdx.y * 32, b = blockIdx.z;
    const int tx = threadIdx.x, ty = threadIdx.y;
#pragma unroll
    for (int i = 0; i < 4; i++)
        tile[ty + 8 * i][tx] =
            img[((size_t)b * CI + c0 + ty + 8 * i) * HW + s0 + tx];
    __syncthreads();
#pragma unroll
    for (int i = 0; i < 4; i++)
        g_imgth[((size_t)b * HW + s0 + ty + 8 * i) * CI + c0 + tx] =
            __float2half(tile[tx][ty + 8 * i]);
}

// W [k][n] fp32 -> g_wth[z][n][k] half (transpose)
__global__ void cvt_w_t(const float* __restrict__ W0,
                        const float* __restrict__ W1,
                        const float* __restrict__ W2,
                        const float* __restrict__ W3) {
    __shared__ float tile[32][33];
    const int z = blockIdx.z;
    const float* W = (z == 0) ? W0 : (z == 1) ? W1 : (z == 2) ? W2 : W3;
    __half* T = g_wth + (size_t)z * 512 * 512;
    const int n0 = blockIdx.x * 32, k0 = blockIdx.y * 32;
    const int tx = threadIdx.x, ty = threadIdx.y;
#pragma unroll
    for (int i = 0; i < 4; i++)
        tile[ty + 8 * i][tx] = W[(size_t)(k0 + ty + 8 * i) * 512 + n0 + tx];
    __syncthreads();
#pragma unroll
    for (int i = 0; i < 4; i++)
        T[(size_t)(n0 + ty + 8 * i) * 512 + k0 + tx] = __float2half(tile[tx][ty + 8 * i]);
}

// audio fp32 -> half, elementwise
__global__ void cvt_aud(const float4* __restrict__ src) {
    const int i = blockIdx.x * blockDim.x + threadIdx.x;
    const float4 v = src[i];
    __half2* dst = (__half2*)g_audh;
    dst[2 * i] = __floats2half2_rn(v.x, v.y);
    dst[2 * i + 1] = __floats2half2_rn(v.z, v.w);
}

// ---------------------------------------------------------------------------
// HGEMM: C[M,512] = A[M,512] @ Wt^T + bias   (A row-major half, Wt [n][k] half)
// 128x128 tile, BK=64, 256 threads (8 warps 2m x 4n), warp tile 64x32,
// m16n8k16 fp16 MMA fp32 accum, 3-stage cp.async, ldmatrix fragment loads,
// fragments double-buffered across k-steps (LDSM latency hidden behind MMAs).
// ---------------------------------------------------------------------------
#define HP 36
#define AB_U32 (128 * HP)            // 4608 u32 per matrix per stage
#define STAGE_U32 (2 * AB_U32)       // 9216
#define STAGE_B (STAGE_U32 * 4)      // 36864
#define GT_SMEM_BYTES (3 * STAGE_B)  // 110592

__device__ __forceinline__ void gt_issue(uint32_t sb, int stage, int kc,
                                         const __half* __restrict__ Ap,
                                         const __half* __restrict__ Bp, int t) {
    const int k0 = kc * 64;
    const uint32_t abase = sb + (uint32_t)stage * STAGE_B;
    const uint32_t bbase = abase + AB_U32 * 4;
#pragma unroll
    for (int r = 0; r < 4; r++) {
        const int idx = t + 256 * r;
        const int row = idx >> 3, j = idx & 7;
        CP_ASYNC16(abase + (uint32_t)(row * HP + 4 * j) * 4,
                   Ap + (size_t)row * 512 + k0 + 8 * j);
    }
#pragma unroll
    for (int r = 0; r < 4; r++) {
        const int idx = t + 256 * r;
        const int row = idx >> 3, j = idx & 7;
        CP_ASYNC16(bbase + (uint32_t)(row * HP + 4 * j) * 4,
                   Bp + (size_t)row * 512 + k0 + 8 * j);
    }
    CP_COMMIT();
}

template <int MODE>
__global__ void __launch_bounds__(256, 2)
gemm_h(const float* __restrict__ bias, const float* __restrict__ bias2) {
    extern __shared__ uint32_t smu[];
    const uint32_t sb = smem_u32(smu);
    const int t = threadIdx.x, warp = t >> 5, lane = t & 31;
    const int g = lane >> 2, tg = lane & 3;
    const int wm = (warp >> 2) * 64, wn = (warp & 3) * 32;
    const int bx = blockIdx.x, by = blockIdx.y;
    const int z = (MODE == 1) ? blockIdx.z : 0;
    if (MODE == 1 && z) bias = bias2;

    const __half* Ap =
        ((MODE == 0) ? g_imgth : (MODE == 3) ? g_attnh : g_audh) +
        (size_t)by * 128 * 512;
    const int wsel = (MODE == 1) ? (1 + z) : MODE;
    const __half* Bp = g_wth + (size_t)wsel * 512 * 512 + (size_t)bx * 128 * 512;

    float acc[4][4][4];
#pragma unroll
    for (int mi = 0; mi < 4; mi++)
#pragma unroll
        for (int ni = 0; ni < 4; ni++)
#pragma unroll
            for (int j = 0; j < 4; j++) acc[mi][ni][j] = 0.f;

    // per-lane ldmatrix byte offsets (within a stage)
    uint32_t a_off[4], b_off[4];
#pragma unroll
    for (int mi = 0; mi < 4; mi++)
        a_off[mi] = (uint32_t)(wm + mi * 16 + (lane & 15)) * 144 +
                    (uint32_t)(lane >> 4) * 16;
#pragma unroll
    for (int ni = 0; ni < 4; ni++)
        b_off[ni] = AB_U32 * 4 +
                    (uint32_t)(wn + ni * 8 + (lane & 7)) * 144 +
                    (uint32_t)((lane >> 3) & 1) * 16;

    gt_issue(sb, 0, 0, Ap, Bp, t);
    gt_issue(sb, 1, 1, Ap, Bp, t);

#pragma unroll 1
    for (int c = 0; c < 8; c++) {
        if (c + 2 < 8) {
            gt_issue(sb, (c + 2) % 3, c + 2, Ap, Bp, t);
            CP_WAIT(2);
        } else if (c == 6) {
            CP_WAIT(1);
        } else {
            CP_WAIT(0);
        }
        __syncthreads();

        const uint32_t stb = sb + (uint32_t)(c % 3) * STAGE_B;
        uint32_t a[2][4][4], b[2][4][2];
#pragma unroll
        for (int mi = 0; mi < 4; mi++) ldsm_x4(a[0][mi], stb + a_off[mi]);
#pragma unroll
        for (int ni = 0; ni < 4; ni++) ldsm_x2(b[0][ni], stb + b_off[ni]);

#pragma unroll
        for (int ks = 0; ks < 4; ks++) {
            const int cur = ks & 1, nxt = cur ^ 1;
            if (ks < 3) {       // prefetch next k-step fragments
                const uint32_t ko = (uint32_t)(ks + 1) * 32;
#pragma unroll
                for (int mi = 0; mi < 4; mi++)
                    ldsm_x4(a[nxt][mi], stb + a_off[mi] + ko);
#pragma unroll
                for (int ni = 0; ni < 4; ni++)
                    ldsm_x2(b[nxt][ni], stb + b_off[ni] + ko);
            }
#pragma unroll
            for (int mi = 0; mi < 4; mi++)
#pragma unroll
                for (int ni = 0; ni < 4; ni++)
                    mma_f16(acc[mi][ni], a[cur][mi], b[cur][ni]);
        }
        __syncthreads();
    }

    // epilogue
    const int rowbase = by * 128;
#pragma unroll
    for (int ni = 0; ni < 4; ni++) {
        const int cb = bx * 128 + wn + ni * 8 + 2 * tg;
        const float2 bv = *(const float2*)&bias[cb];
#pragma unroll
        for (int mi = 0; mi < 4; mi++) {
            const int r0 = rowbase + wm + mi * 16 + g;
            if (MODE == 3) {
                float2 o0, o1;
                o0.x = acc[mi][ni][0] + bv.x; o0.y = acc[mi][ni][1] + bv.y;
                o1.x = acc[mi][ni][2] + bv.x; o1.y = acc[mi][ni][3] + bv.y;
                *(float2*)&g_y[(size_t)r0 * 512 + cb] = o0;
                *(float2*)&g_y[(size_t)(r0 + 8) * 512 + cb] = o1;
            } else {
                __half* C = (MODE == 0) ? g_qh : (z == 0) ? g_kh : g_vh;
                const __half2 h0 =
                    __floats2half2_rn(acc[mi][ni][0] + bv.x, acc[mi][ni][1] + bv.y);
                const __half2 h1 =
                    __floats2half2_rn(acc[mi][ni][2] + bv.x, acc[mi][ni][3] + bv.y);
                *(__half2*)&C[(size_t)r0 * 512 + cb] = h0;
                *(__half2*)&C[(size_t)(r0 + 8) * 512 + cb] = h1;
            }
        }
    }
}

// ---------------------------------------------------------------------------
// Tensor-core attention (all fp16 inputs, fp32 accum/softmax):
// block = (b,h) x 128 q-rows, 256 threads, 8 warps, 16 q-rows/warp.
// ---------------------------------------------------------------------------
#define QS_OFF 0
#define KS_OFF (128 * 36)
#define V2_OFF (KS_OFF + 256 * 36)
#define ATTN_SMEM_BYTES ((V2_OFF + 128 * 72) * 4)

__global__ void __launch_bounds__(256, 1) attn_tc() {
    extern __shared__ uint32_t smu[];
    uint32_t* Qs = smu + QS_OFF;
    uint32_t* Ks = smu + KS_OFF;
    __half2* V2 = (__half2*)(smu + V2_OFF);

    const int b = blockIdx.x >> 3, h = blockIdx.x & 7;
    const int q0 = blockIdx.y << 7;
    const int t = threadIdx.x, warp = t >> 5, lane = t & 31;
    const int g = lane >> 2, tg = lane & 3;

    const __half* qb = g_qh + (size_t)(b * HW + q0) * CA + h * 64;
    const __half* kb = g_kh + (size_t)b * (KL * CA) + h * 64;
    const __half* vb = g_vh + (size_t)b * (KL * CA) + h * 64;

#pragma unroll
    for (int r = 0; r < 4; r++) {        // Q: 128 rows x 8 xfers
        const int idx = t + 256 * r;
        const int row = idx >> 3, j = idx & 7;
        *(uint4*)&Qs[row * 36 + 4 * j] =
            *(const uint4*)(qb + (size_t)row * CA + 8 * j);
    }
#pragma unroll
    for (int r = 0; r < 8; r++) {        // K: 256 rows x 8 xfers
        const int idx = t + 256 * r;
        const int row = idx >> 3, j = idx & 7;
        *(uint4*)&Ks[row * 36 + 4 * j] =
            *(const uint4*)(kb + (size_t)row * CA + 8 * j);
    }
#pragma unroll
    for (int r = 0; r < 16; r++) {       // V -> half2 key-pairs
        const int idx = t + 256 * r;
        const int kp = idx >> 5, d2 = idx & 31;
        const __half2 a = *(const __half2*)(vb + (size_t)(2 * kp) * CA + 2 * d2);
        const __half2 c = *(const __half2*)(vb + (size_t)(2 * kp + 1) * CA + 2 * d2);
        V2[kp * 72 + 2 * d2] = __halves2half2(__low2half(a), __low2half(c));
        V2[kp * 72 + 2 * d2 + 1] = __halves2half2(__high2half(a), __high2half(c));
    }
    __syncthreads();

    // Q fragments (4 k16-steps over d=64)
    uint32_t qf[4][4];
    const uint32_t* qw = Qs + warp * 16 * 36;
#pragma unroll
    for (int kc = 0; kc < 4; kc++) {
        const int hk = kc * 8 + tg;
        qf[kc][0] = qw[g * 36 + hk];
        qf[kc][1] = qw[(g + 8) * 36 + hk];
        qf[kc][2] = qw[g * 36 + hk + 4];
        qf[kc][3] = qw[(g + 8) * 36 + hk + 4];
    }

    // --- S = Q K^T ---
    float sc[32][4];
#pragma unroll
    for (int j = 0; j < 32; j++)
#pragma unroll
        for (int i = 0; i < 4; i++) sc[j][i] = 0.f;

#pragma unroll
    for (int j = 0; j < 32; j++) {       // key octet j
        const uint32_t* kr = Ks + (j * 8 + g) * 36;
#pragma unroll
        for (int kc = 0; kc < 4; kc++) {
            uint32_t bf[2];
            bf[0] = kr[kc * 8 + tg];
            bf[1] = kr[kc * 8 + tg + 4];
            mma_f16(sc[j], qf[kc], bf);
        }
    }

    // --- softmax (rows g, g+8; scale = 0.125) ---
    uint32_t pl[32], ph[32];
    {
        float m0 = -1e30f, m1 = -1e30f;
#pragma unroll
        for (int j = 0; j < 32; j++) {
            m0 = fmaxf(m0, fmaxf(sc[j][0], sc[j][1]));
            m1 = fmaxf(m1, fmaxf(sc[j][2], sc[j][3]));
        }
        m0 = fmaxf(m0, __shfl_xor_sync(0xffffffffu, m0, 1));
        m0 = fmaxf(m0, __shfl_xor_sync(0xffffffffu, m0, 2));
        m1 = fmaxf(m1, __shfl_xor_sync(0xffffffffu, m1, 1));
        m1 = fmaxf(m1, __shfl_xor_sync(0xffffffffu, m1, 2));
        float s0 = 0.f, s1 = 0.f;
#pragma unroll
        for (int j = 0; j < 32; j++) {
            sc[j][0] = __expf(0.125f * (sc[j][0] - m0));
            sc[j][1] = __expf(0.125f * (sc[j][1] - m0));
            sc[j][2] = __expf(0.125f * (sc[j][2] - m1));
            sc[j][3] = __expf(0.125f * (sc[j][3] - m1));
            s0 += sc[j][0] + sc[j][1];
            s1 += sc[j][2] + sc[j][3];
        }
        s0 += __shfl_xor_sync(0xffffffffu, s0, 1);
        s0 += __shfl_xor_sync(0xffffffffu, s0, 2);
        s1 += __shfl_xor_sync(0xffffffffu, s1, 1);
        s1 += __shfl_xor_sync(0xffffffffu, s1, 2);
        const float i0 = __frcp_rn(s0), i1 = __frcp_rn(s1);
#pragma unroll
        for (int j = 0; j < 32; j++) {
            const __half2 lo = __floats2half2_rn(sc[j][0] * i0, sc[j][1] * i0);
            const __half2 hi = __floats2half2_rn(sc[j][2] * i1, sc[j][3] * i1);
            pl[j] = *(const uint32_t*)&lo;
            ph[j] = *(const uint32_t*)&hi;
        }
    }

    // --- O = P V ---
    float oc[8][4];
#pragma unroll
    for (int ni = 0; ni < 8; ni++)
#pragma unroll
        for (int i = 0; i < 4; i++) oc[ni][i] = 0.f;

#pragma unroll
    for (int kc = 0; kc < 16; kc++) {
        uint32_t a[4];
        a[0] = pl[2 * kc];
        a[1] = ph[2 * kc];
        a[2] = pl[2 * kc + 1];
        a[3] = ph[2 * kc + 1];
        const __half2* vr0 = V2 + (kc * 8 + tg) * 72;
        const __half2* vr1 = V2 + (kc * 8 + tg + 4) * 72;
#pragma unroll
        for (int ni = 0; ni < 8; ni++) {
            uint32_t bf[2];
            bf[0] = *(const uint32_t*)&vr0[ni * 8 + g];
            bf[1] = *(const uint32_t*)&vr1[ni * 8 + g];
            mma_f16(oc[ni], a, bf);
        }
    }

    __half* ob = g_attnh + (size_t)(b * HW + q0 + warp * 16) * CA + h * 64;
#pragma unroll
    for (int ni = 0; ni < 8; ni++) {
        const int col = ni * 8 + 2 * tg;
        *(__half2*)&ob[(size_t)g * CA + col] =
            __floats2half2_rn(oc[ni][0], oc[ni][1]);
        *(__half2*)&ob[(size_t)(g + 8) * CA + col] =
            __floats2half2_rn(oc[ni][2], oc[ni][3]);
    }
}

// ---------------------------------------------------------------------------
// Residual + LayerNorm + transpose to [b, c, h, w].
// ---------------------------------------------------------------------------
#define LN_SMEM_BYTES (32 * 513 * 4)

__global__ void __launch_bounds__(256, 1)
ln_kernel(const float* __restrict__ img, const float* __restrict__ gamma,
          const float* __restrict__ beta, float* __restrict__ out) {
    extern __shared__ float sm[];   // [32][513]
    __shared__ float smu2[32], srv[32];
    const int b = blockIdx.x >> 5;
    const int s0 = (blockIdx.x & 31) << 5;
    const int t = threadIdx.x;

#pragma unroll
    for (int r = 0; r < 16; r++) {
        const int u = t + 256 * r;
        const int s = u >> 7, c4 = (u & 127) << 2;
        const float4 v = *(const float4*)&g_y[((size_t)(b * HW + s0 + s)) * CI + c4];
        float* dst = sm + s * 513 + c4;
        dst[0] = v.x; dst[1] = v.y; dst[2] = v.z; dst[3] = v.w;
    }
    __syncthreads();
#pragma unroll 8
    for (int r = 0; r < 64; r++) {
        const int u = t + 256 * r;
        const int c = u >> 5, s = u & 31;
        sm[s * 513 + c] += img[(size_t)b * (CI * HW) + (size_t)c * HW + s0 + s];
    }
    __syncthreads();

    const int warp = t >> 5, lane = t & 31;
#pragma unroll
    for (int rr = 0; rr < 4; rr++) {
        const int s = warp * 4 + rr;
        const float* row = sm + s * 513;
        float sum = 0.f;
#pragma unroll
        for (int i = 0; i < 16; i++) sum += row[lane + 32 * i];
#pragma unroll
        for (int off = 16; off > 0; off >>= 1)
            sum += __shfl_xor_sync(0xffffffffu, sum, off);
        const float mu = sum * (1.0f / 512.0f);
        float var = 0.f;
#pragma unroll
        for (int i = 0; i < 16; i++) {
            const float d = row[lane + 32 * i] - mu;
            var += d * d;
        }
#pragma unroll
        for (int off = 16; off > 0; off >>= 1)
            var += __shfl_xor_sync(0xffffffffu, var, off);
        var *= (1.0f / 512.0f);
        if (lane == 0) { smu2[s] = mu; srv[s] = rsqrtf(var + 1e-5f); }
    }
    __syncthreads();

    const float mu = smu2[lane], rv = srv[lane];
#pragma unroll 4
    for (int ci = 0; ci < 64; ci++) {
        const int c = warp * 64 + ci;
        const float val = (sm[lane * 513 + c] - mu) * rv * gamma[c] + beta[c];
        out[(size_t)b * (CI * HW) + (size_t)c * HW + s0 + lane] = val;
    }
}

// ---------------------------------------------------------------------------
extern "C" void kernel_launch(void* const* d_in, const int* in_sizes, int n_in,
                              void* d_out, int out_size) {
    (void)in_sizes; (void)n_in; (void)out_size;
    const float* img   = (const float*)d_in[0];
    const float* aud   = (const float*)d_in[1];
    const float* Wq    = (const float*)d_in[2];
    const float* bq    = (const float*)d_in[3];
    const float* Wk    = (const float*)d_in[4];
    const float* bk    = (const float*)d_in[5];
    const float* Wv    = (const float*)d_in[6];
    const float* bv    = (const float*)d_in[7];
    const float* Wo    = (const float*)d_in[8];
    const float* bo    = (const float*)d_in[9];
    const float* gamma = (const float*)d_in[10];
    const float* beta  = (const float*)d_in[11];
    float* out = (float*)d_out;

    cudaFuncSetAttribute((const void*)gemm_h<0>,
                         cudaFuncAttributeMaxDynamicSharedMemorySize, GT_SMEM_BYTES);
    cudaFuncSetAttribute((const void*)gemm_h<1>,
                         cudaFuncAttributeMaxDynamicSharedMemorySize, GT_SMEM_BYTES);
    cudaFuncSetAttribute((const void*)gemm_h<3>,
                         cudaFuncAttributeMaxDynamicSharedMemorySize, GT_SMEM_BYTES);
    cudaFuncSetAttribute((const void*)attn_tc,
                         cudaFuncAttributeMaxDynamicSharedMemorySize, ATTN_SMEM_BYTES);
    cudaFuncSetAttribute((const void*)ln_kernel,
                         cudaFuncAttributeMaxDynamicSharedMemorySize, LN_SMEM_BYTES);

    // Side streams + events for fork/join concurrency inside the captured
    // graph. Lazily created host-side resources; the captured work (kernel
    // nodes + dependencies) is identical on every call.
    static cudaStream_t s1 = nullptr, s2 = nullptr;
    static cudaEvent_t ev0 = nullptr, evW = nullptr, evKV = nullptr;
    if (!s1) {
        cudaStreamCreateWithFlags(&s1, cudaStreamNonBlocking);
        cudaStreamCreateWithFlags(&s2, cudaStreamNonBlocking);
        cudaEventCreateWithFlags(&ev0, cudaEventDisableTiming);
        cudaEventCreateWithFlags(&evW, cudaEventDisableTiming);
        cudaEventCreateWithFlags(&evKV, cudaEventDisableTiming);
    }

    // Fork s1 (weights) and s2 (audio) off the main stream.
    cudaEventRecord(ev0, 0);
    cudaStreamWaitEvent(s1, ev0, 0);
    cudaStreamWaitEvent(s2, ev0, 0);

    cvt_w_t<<<dim3(16, 16, 4), dim3(32, 8), 0, s1>>>(Wq, Wk, Wv, Wo);
    cudaEventRecord(evW, s1);

    cvt_aud<<<NB * KL * CA / 4 / 256, 256, 0, s2>>>((const float4*)aud);

    cvt_img_t<<<dim3(16, 32, 16), dim3(32, 8)>>>(img);      // main stream

    // Q GEMM on main stream (needs img + W)
    cudaStreamWaitEvent(0, evW, 0);
    gemm_h<0><<<dim3(4, 128), 256, GT_SMEM_BYTES>>>(bq, nullptr);

    // K+V GEMM on s2, concurrent with Q GEMM (needs aud + W)
    cudaStreamWaitEvent(s2, evW, 0);
    gemm_h<1><<<dim3(4, 32, 2), 256, GT_SMEM_BYTES, s2>>>(bk, bv);
    cudaEventRecord(evKV, s2);

    // Join: attention needs Q (main) and K/V (s2)
    cudaStreamWaitEvent(0, evKV, 0);
    attn_tc<<<dim3(128, 8), 256, ATTN_SMEM_BYTES>>>();
    gemm_h<3><<<dim3(4, 128), 256, GT_SMEM_BYTES>>>(bo, nullptr);
    ln_kernel<<<512, 256, LN_SMEM_BYTES>>>(img, gamma, beta, out);
}